// round 7
// baseline (speedup 1.0000x reference)
#include <cuda_runtime.h>
#include <cstdint>

// ScaledDotProductAttention  B=4 H=16 S=2048 D=64
// out = [output (B,H,S,D) | attn (B,H,S,S)] f32.
// Single-pass mma.sync tf32 (m32n64 warp tiles), cp.async double-buffered K/V,
// shfl P remap, unnormalized attn + normalize pass.
// R7: one-shot in-place tf32 convert of K/V per tile; pair-permuted Q/K layout
//     so A and K-B fragments are single LDS.64 ops (no cvt on the MMA path).

#define NEG_INF -1000000000.0f

static constexpr int Bv = 4, Hv = 16, Sv = 2048, Dv = 64;
static constexpr int BM = 128, BN = 64, THREADS = 128, NKT = Sv / BN;
static constexpr int LDSK = 68;  // padded row stride (floats)

// smem byte offsets: Q | K0 | K1 | V0 | V1
static constexpr int SQ  = 0;
static constexpr int TILE_B = BN * LDSK * 4;          // 17408
static constexpr int SK0 = BM * LDSK * 4;             // 34816
static constexpr int SK1 = SK0 + TILE_B;
static constexpr int SV0 = SK1 + TILE_B;
static constexpr int SV1 = SV0 + TILE_B;
static constexpr int SMEM_TOTAL = SV1 + TILE_B;       // 104448

__device__ float g_inv[Bv * Hv * Sv];   // per-row 1/lsum scratch

__device__ __forceinline__ uint32_t s2u(const void* p) {
    uint32_t a;
    asm("{ .reg .u64 t; cvta.to.shared.u64 t, %1; cvt.u32.u64 %0, t; }" : "=r"(a) : "l"(p));
    return a;
}
__device__ __forceinline__ void cpa16(uint32_t dst, const void* src) {
    asm volatile("cp.async.cg.shared.global [%0], [%1], 16;" :: "r"(dst), "l"(src));
}
__device__ __forceinline__ uint32_t f2tf(float f) {
    uint32_t u;
    asm("cvt.rna.tf32.f32 %0, %1;" : "=r"(u) : "f"(f));
    return u;
}
__device__ __forceinline__ void st_cs2(float* p, float x, float y) {
    asm volatile("st.global.cs.v2.f32 [%0], {%1, %2};" :: "l"(p), "f"(x), "f"(y) : "memory");
}
__device__ __forceinline__ void mma8(float c[4], const uint32_t a[4], uint32_t b0, uint32_t b1) {
    asm volatile(
        "mma.sync.aligned.m16n8k8.row.col.f32.tf32.tf32.f32 "
        "{%0,%1,%2,%3}, {%4,%5,%6,%7}, {%8,%9}, {%0,%1,%2,%3};"
        : "+f"(c[0]), "+f"(c[1]), "+f"(c[2]), "+f"(c[3])
        : "r"(a[0]), "r"(a[1]), "r"(a[2]), "r"(a[3]), "r"(b0), "r"(b1));
}

__global__ __launch_bounds__(THREADS, 2)
void ScaledDotProductAttention_30253749633177_kernel(
    const float* __restrict__ q, const float* __restrict__ k,
    const float* __restrict__ v, const int* __restrict__ mask,
    const float* __restrict__ bias, float* __restrict__ out)
{
    extern __shared__ char smem[];
    const uint32_t sb = s2u(smem);
    uint32_t* sQ = (uint32_t*)(smem + SQ);

    const int b  = blockIdx.x & 3;      // (b,h) collapsed for mask+bias L2 co-residency
    const int h  = blockIdx.x >> 2;
    const int qt = blockIdx.y;
    const int tid = threadIdx.x;
    const int wid = tid >> 5, lane = tid & 31;
    const int g = lane >> 2, t4 = lane & 3;
    const int qbase = qt * BM, wrow = wid * 32;

    const size_t bh = (size_t)(b * Hv + h);
    const float* qp    = q + bh * Sv * Dv;
    const float* kp    = k + bh * Sv * Dv;
    const float* vp    = v + bh * Sv * Dv;
    const float* biasp = bias + (size_t)h * Sv * Sv;
    const int*   maskp = mask + (size_t)b * Sv * Sv;
    float* op = out + bh * Sv * Dv;
    float* ap = out + (size_t)Bv * Hv * Sv * Dv + bh * (size_t)Sv * Sv;

    // ---- group 0: Q + K0 + V0 ----
    for (int i = tid; i < BM * Dv / 4; i += THREADS) {
        int r = i >> 4, c = (i & 15) * 4;
        cpa16(sb + SQ + (r * LDSK + c) * 4, qp + (size_t)(qbase + r) * Dv + c);
    }
    for (int i = tid; i < BN * Dv / 4; i += THREADS) {
        int r = i >> 4, c = (i & 15) * 4;
        cpa16(sb + SK0 + (r * LDSK + c) * 4, kp + (size_t)r * Dv + c);
        cpa16(sb + SV0 + (r * LDSK + c) * 4, vp + (size_t)r * Dv + c);
    }
    asm volatile("cp.async.commit_group;" ::: "memory");

    // wait group 0; convert+pair-permute Q in place (once, one row per thread)
    asm volatile("cp.async.wait_group 0;" ::: "memory");
    __syncthreads();
    {
        uint32_t* qr = sQ + tid * LDSK;
        float f[64];
        #pragma unroll
        for (int i = 0; i < 16; i++) {
            float4 x = *reinterpret_cast<const float4*>(qr + i * 4);
            f[i*4+0] = x.x; f[i*4+1] = x.y; f[i*4+2] = x.z; f[i*4+3] = x.w;
        }
        #pragma unroll
        for (int b8 = 0; b8 < 8; b8++)
            #pragma unroll
            for (int i = 0; i < 4; i++) {
                qr[b8*8 + 2*i]     = f2tf(f[b8*8 + i]);
                qr[b8*8 + 2*i + 1] = f2tf(f[b8*8 + i + 4]);
            }
    }
    __syncthreads();

    const uint32_t* sQr0 = sQ + (wrow + g) * LDSK;        // pair-permuted rows
    const uint32_t* sQr1 = sQ + (wrow + 16 + g) * LDSK;
    const int rA0 = qbase + wrow + g;
    const int rA1 = qbase + wrow + 16 + g;

    const int srcA = (lane & 28) | (t4 >> 1);
    const int srcB = srcA + 2;
    const int sel  = t4 & 1;

    float ls[2][2] = {{0.f, 0.f}, {0.f, 0.f}};
    float o[2][8][4];
    #pragma unroll
    for (int mb = 0; mb < 2; mb++)
        #pragma unroll
        for (int dt = 0; dt < 8; dt++)
            o[mb][dt][0] = o[mb][dt][1] = o[mb][dt][2] = o[mb][dt][3] = 0.f;

    for (int kt = 0; kt < NKT; kt++) {
        const int cur = kt & 1;
        // prefetch next tile into the other buffer
        if (kt + 1 < NKT) {
            const uint32_t dk = sb + (cur ? SK0 : SK1);
            const uint32_t dv = sb + (cur ? SV0 : SV1);
            const float* ks = kp + (size_t)(kt + 1) * BN * Dv;
            const float* vs = vp + (size_t)(kt + 1) * BN * Dv;
            for (int i = tid; i < BN * Dv / 4; i += THREADS) {
                int r = i >> 4, c = (i & 15) * 4;
                cpa16(dk + (r * LDSK + c) * 4, ks + (size_t)r * Dv + c);
                cpa16(dv + (r * LDSK + c) * 4, vs + (size_t)r * Dv + c);
            }
            asm volatile("cp.async.commit_group;" ::: "memory");
            asm volatile("cp.async.wait_group 1;" ::: "memory");
        } else {
            asm volatile("cp.async.wait_group 0;" ::: "memory");
        }
        __syncthreads();

        uint32_t* sK = (uint32_t*)(smem + (cur ? SK1 : SK0));
        uint32_t* sV = (uint32_t*)(smem + (cur ? SV1 : SV0));

        // ---- one-shot convert: K pair-permuted, V plain cvt (in place; half-row/thread) ----
        {
            const int row = tid >> 1, hf = (tid & 1) * 32;
            uint32_t* kr = sK + row * LDSK + hf;
            float fk[32];
            #pragma unroll
            for (int i = 0; i < 8; i++) {
                float4 x = *reinterpret_cast<const float4*>(kr + i * 4);
                fk[i*4+0] = x.x; fk[i*4+1] = x.y; fk[i*4+2] = x.z; fk[i*4+3] = x.w;
            }
            #pragma unroll
            for (int b8 = 0; b8 < 4; b8++)
                #pragma unroll
                for (int i = 0; i < 4; i++) {
                    kr[b8*8 + 2*i]     = f2tf(fk[b8*8 + i]);
                    kr[b8*8 + 2*i + 1] = f2tf(fk[b8*8 + i + 4]);
                }
            uint32_t* vr = sV + row * LDSK + hf;
            #pragma unroll
            for (int i = 0; i < 8; i++) {
                float4 x = *reinterpret_cast<const float4*>(vr + i * 4);
                uint4 u = make_uint4(f2tf(x.x), f2tf(x.y), f2tf(x.z), f2tf(x.w));
                *reinterpret_cast<uint4*>(vr + i * 4) = u;
            }
        }
        __syncthreads();

        // ---- QK (vectorized fragment loads, no cvt) ----
        float acc[2][8][4];
        #pragma unroll
        for (int mb = 0; mb < 2; mb++)
            #pragma unroll
            for (int nt = 0; nt < 8; nt++)
                acc[mb][nt][0] = acc[mb][nt][1] = acc[mb][nt][2] = acc[mb][nt][3] = 0.f;

        #pragma unroll
        for (int kk = 0; kk < 8; kk++) {
            const int co = kk * 8 + 2 * t4;
            uint32_t a0[4], a1[4];
            uint2 p0 = *reinterpret_cast<const uint2*>(sQr0 + co);
            uint2 p1 = *reinterpret_cast<const uint2*>(sQr0 + 8 * LDSK + co);
            uint2 p2 = *reinterpret_cast<const uint2*>(sQr1 + co);
            uint2 p3 = *reinterpret_cast<const uint2*>(sQr1 + 8 * LDSK + co);
            a0[0] = p0.x; a0[2] = p0.y; a0[1] = p1.x; a0[3] = p1.y;
            a1[0] = p2.x; a1[2] = p2.y; a1[1] = p3.x; a1[3] = p3.y;
            #pragma unroll
            for (int nt = 0; nt < 8; nt++) {
                uint2 bb = *reinterpret_cast<const uint2*>(sK + (nt * 8 + g) * LDSK + co);
                mma8(acc[0][nt], a0, bb.x, bb.y);
                mma8(acc[1][nt], a1, bb.x, bb.y);
            }
        }

        // ---- epilogue: e = exp(masked score + bias), unnormalized streaming attn write ----
        #pragma unroll
        for (int mb = 0; mb < 2; mb++) {
            const int rowA = (mb ? rA1 : rA0);
            const int rowB = rowA + 8;
            #pragma unroll
            for (int nt = 0; nt < 8; nt++) {
                int col = kt * BN + nt * 8 + 2 * t4;
                float2 bA = *reinterpret_cast<const float2*>(biasp + (size_t)rowA * Sv + col);
                float2 bB = *reinterpret_cast<const float2*>(biasp + (size_t)rowB * Sv + col);
                int2 mA = *reinterpret_cast<const int2*>(maskp + (size_t)rowA * Sv + col);
                int2 mB = *reinterpret_cast<const int2*>(maskp + (size_t)rowB * Sv + col);
                float s0 = (mA.x ? acc[mb][nt][0] * 0.125f : NEG_INF) + bA.x;
                float s1 = (mA.y ? acc[mb][nt][1] * 0.125f : NEG_INF) + bA.y;
                float s2 = (mB.x ? acc[mb][nt][2] * 0.125f : NEG_INF) + bB.x;
                float s3 = (mB.y ? acc[mb][nt][3] * 0.125f : NEG_INF) + bB.y;
                float e0 = __expf(fminf(s0, 60.f));
                float e1 = __expf(fminf(s1, 60.f));
                float e2 = __expf(fminf(s2, 60.f));
                float e3 = __expf(fminf(s3, 60.f));
                st_cs2(ap + (size_t)rowA * Sv + col, e0, e1);
                st_cs2(ap + (size_t)rowB * Sv + col, e2, e3);
                ls[mb][0] += e0 + e1;
                ls[mb][1] += e2 + e3;
                acc[mb][nt][0] = e0; acc[mb][nt][1] = e1;
                acc[mb][nt][2] = e2; acc[mb][nt][3] = e3;
            }
        }

        // ---- PV: remap acc (C-frag) -> A-frag via shuffles, rna-round, accumulate O ----
        #pragma unroll
        for (int kk = 0; kk < 8; kk++) {
            uint32_t a0[4], a1[4];
            {
                float u0 = __shfl_sync(0xffffffffu, acc[0][kk][0], srcA);
                float u1 = __shfl_sync(0xffffffffu, acc[0][kk][1], srcA);
                float u2 = __shfl_sync(0xffffffffu, acc[0][kk][2], srcA);
                float u3 = __shfl_sync(0xffffffffu, acc[0][kk][3], srcA);
                float w0 = __shfl_sync(0xffffffffu, acc[0][kk][0], srcB);
                float w1 = __shfl_sync(0xffffffffu, acc[0][kk][1], srcB);
                float w2 = __shfl_sync(0xffffffffu, acc[0][kk][2], srcB);
                float w3 = __shfl_sync(0xffffffffu, acc[0][kk][3], srcB);
                a0[0] = f2tf(sel ? u1 : u0);  a0[1] = f2tf(sel ? u3 : u2);
                a0[2] = f2tf(sel ? w1 : w0);  a0[3] = f2tf(sel ? w3 : w2);
            }
            {
                float u0 = __shfl_sync(0xffffffffu, acc[1][kk][0], srcA);
                float u1 = __shfl_sync(0xffffffffu, acc[1][kk][1], srcA);
                float u2 = __shfl_sync(0xffffffffu, acc[1][kk][2], srcA);
                float u3 = __shfl_sync(0xffffffffu, acc[1][kk][3], srcA);
                float w0 = __shfl_sync(0xffffffffu, acc[1][kk][0], srcB);
                float w1 = __shfl_sync(0xffffffffu, acc[1][kk][1], srcB);
                float w2 = __shfl_sync(0xffffffffu, acc[1][kk][2], srcB);
                float w3 = __shfl_sync(0xffffffffu, acc[1][kk][3], srcB);
                a1[0] = f2tf(sel ? u1 : u0);  a1[1] = f2tf(sel ? u3 : u2);
                a1[2] = f2tf(sel ? w1 : w0);  a1[3] = f2tf(sel ? w3 : w2);
            }
            #pragma unroll
            for (int dt = 0; dt < 8; dt++) {
                const uint32_t* vb = sV + (kk * 8 + t4) * LDSK + dt * 8 + g;
                uint32_t b0 = vb[0], b1 = vb[4 * LDSK];
                mma8(o[0][dt], a0, b0, b1);
                mma8(o[1][dt], a1, b0, b1);
            }
        }
        __syncthreads();  // done reading bufs before next iter's prefetch overwrites
    }

    // ---- row sums -> inverses (reduce across t4 quad) ----
    #pragma unroll
    for (int mb = 0; mb < 2; mb++) {
        ls[mb][0] += __shfl_xor_sync(0xffffffffu, ls[mb][0], 1);
        ls[mb][0] += __shfl_xor_sync(0xffffffffu, ls[mb][0], 2);
        ls[mb][1] += __shfl_xor_sync(0xffffffffu, ls[mb][1], 1);
        ls[mb][1] += __shfl_xor_sync(0xffffffffu, ls[mb][1], 2);
    }
    const float il[2][2] = {{1.f / ls[0][0], 1.f / ls[0][1]},
                            {1.f / ls[1][0], 1.f / ls[1][1]}};

    // stash inverses for the normalize kernel
    if (t4 == 0) {
        #pragma unroll
        for (int mb = 0; mb < 2; mb++) {
            const int rowA = (mb ? rA1 : rA0);
            g_inv[bh * Sv + rowA]     = il[mb][0];
            g_inv[bh * Sv + rowA + 8] = il[mb][1];
        }
    }

    // ---- write O (normalized) ----
    #pragma unroll
    for (int mb = 0; mb < 2; mb++) {
        const int rowA = (mb ? rA1 : rA0);
        const int rowB = rowA + 8;
        #pragma unroll
        for (int dt = 0; dt < 8; dt++) {
            int col = dt * 8 + 2 * t4;
            *reinterpret_cast<float2*>(op + (size_t)rowA * Dv + col) =
                make_float2(o[mb][dt][0] * il[mb][0], o[mb][dt][1] * il[mb][0]);
            *reinterpret_cast<float2*>(op + (size_t)rowB * Dv + col) =
                make_float2(o[mb][dt][2] * il[mb][1], o[mb][dt][3] * il[mb][1]);
        }
    }
}

// ---- pass 2: attn[row] *= 1/lsum[row] (pure stream, single-touch hints) ----
__global__ __launch_bounds__(256)
void sdpa_normalize_kernel(float4* __restrict__ attn, int64_t total4)
{
    int64_t stride = (int64_t)gridDim.x * blockDim.x;
    for (int64_t i = (int64_t)blockIdx.x * blockDim.x + threadIdx.x; i < total4; i += stride) {
        float inv = g_inv[i >> 9];   // 512 float4 per 2048-col row
        float4 vv = __ldcs(attn + i);
        vv.x *= inv; vv.y *= inv; vv.z *= inv; vv.w *= inv;
        __stcs(attn + i, vv);
    }
}

extern "C" void kernel_launch(void* const* d_in, const int* in_sizes, int n_in,
                              void* d_out, int out_size)
{
    const float* q    = (const float*)d_in[0];
    const float* k    = (const float*)d_in[1];
    const float* v    = (const float*)d_in[2];
    const int*   mask = (const int*)d_in[3];
    const float* bias = (const float*)d_in[4];
    float* out = (float*)d_out;

    cudaFuncSetAttribute(ScaledDotProductAttention_30253749633177_kernel,
                         cudaFuncAttributeMaxDynamicSharedMemorySize, SMEM_TOTAL);

    dim3 grid(Bv * Hv, Sv / BM);   // x = all (b,h) for one qt -> mask+bias L2 co-residency
    ScaledDotProductAttention_30253749633177_kernel<<<grid, THREADS, SMEM_TOTAL>>>(
        q, k, v, mask, bias, out);

    float4* attn = (float4*)(out + (size_t)Bv * Hv * Sv * Dv);
    int64_t total4 = (int64_t)Bv * Hv * Sv * Sv / 4;
    sdpa_normalize_kernel<<<8192, 256>>>(attn, total4);
}

// round 8
// speedup vs baseline: 1.2139x; 1.2139x over previous
#include <cuda_runtime.h>
#include <cstdint>

// ScaledDotProductAttention  B=4 H=16 S=2048 D=64
// out = [output (B,H,S,D) | attn (B,H,S,S)] f32.
// R8 = R6 (best) + bit-packed mask (pre-pass + uint2 loads in epilogue).
// Single-pass mma.sync tf32 (m32n64 warp tiles), cp.async double-buffered K/V,
// shfl P remap, rna rounding, unnormalized attn + normalize pass.

#define NEG_INF -1000000000.0f

static constexpr int Bv = 4, Hv = 16, Sv = 2048, Dv = 64;
static constexpr int BM = 128, BN = 64, THREADS = 128, NKT = Sv / BN;
static constexpr int LDSK = 68;  // padded row stride (floats)

// smem byte offsets: Q | K0 | K1 | V0 | V1
static constexpr int SQ  = 0;
static constexpr int TILE_B = BN * LDSK * 4;          // 17408
static constexpr int SK0 = BM * LDSK * 4;             // 34816
static constexpr int SK1 = SK0 + TILE_B;
static constexpr int SV0 = SK1 + TILE_B;
static constexpr int SV1 = SV0 + TILE_B;
static constexpr int SMEM_TOTAL = SV1 + TILE_B;       // 104448

static constexpr int MASK_WORDS_PER_ROW = Sv / 32;    // 64

__device__ float    g_inv[Bv * Hv * Sv];                       // per-row 1/lsum
__device__ uint32_t g_mask[Bv * Sv * MASK_WORDS_PER_ROW];      // packed mask bits (2 MB)

__device__ __forceinline__ uint32_t s2u(const void* p) {
    uint32_t a;
    asm("{ .reg .u64 t; cvta.to.shared.u64 t, %1; cvt.u32.u64 %0, t; }" : "=r"(a) : "l"(p));
    return a;
}
__device__ __forceinline__ void cpa16(uint32_t dst, const void* src) {
    asm volatile("cp.async.cg.shared.global [%0], [%1], 16;" :: "r"(dst), "l"(src));
}
__device__ __forceinline__ uint32_t f2tf(float f) {
    uint32_t u;
    asm("cvt.rna.tf32.f32 %0, %1;" : "=r"(u) : "f"(f));
    return u;
}
__device__ __forceinline__ void st_cs2(float* p, float x, float y) {
    asm volatile("st.global.cs.v2.f32 [%0], {%1, %2};" :: "l"(p), "f"(x), "f"(y) : "memory");
}
__device__ __forceinline__ void mma8(float c[4], const uint32_t a[4], uint32_t b0, uint32_t b1) {
    asm volatile(
        "mma.sync.aligned.m16n8k8.row.col.f32.tf32.tf32.f32 "
        "{%0,%1,%2,%3}, {%4,%5,%6,%7}, {%8,%9}, {%0,%1,%2,%3};"
        : "+f"(c[0]), "+f"(c[1]), "+f"(c[2]), "+f"(c[3])
        : "r"(a[0]), "r"(a[1]), "r"(a[2]), "r"(a[3]), "r"(b0), "r"(b1));
}

// ---- pass 0: pack mask to bits (one warp per 32-col word) ----
__global__ __launch_bounds__(256)
void sdpa_pack_mask_kernel(const int* __restrict__ mask)
{
    int gw   = (blockIdx.x * blockDim.x + threadIdx.x) >> 5;   // word index
    int lane = threadIdx.x & 31;
    int w  = gw & (MASK_WORDS_PER_ROW - 1);
    int rs = gw >> 6;                                           // b*Sv + s
    int mv = mask[(size_t)rs * Sv + w * 32 + lane];
    uint32_t bits = __ballot_sync(0xffffffffu, mv != 0);
    if (lane == 0) g_mask[gw] = bits;
}

__global__ __launch_bounds__(THREADS, 2)
void ScaledDotProductAttention_30253749633177_kernel(
    const float* __restrict__ q, const float* __restrict__ k,
    const float* __restrict__ v, const float* __restrict__ bias,
    float* __restrict__ out)
{
    extern __shared__ char smem[];
    const uint32_t sb = s2u(smem);
    uint32_t* sQ = (uint32_t*)(smem + SQ);

    const int b  = blockIdx.x & 3;      // (b,h) collapsed for mask+bias L2 co-residency
    const int h  = blockIdx.x >> 2;
    const int qt = blockIdx.y;
    const int tid = threadIdx.x;
    const int wid = tid >> 5, lane = tid & 31;
    const int g = lane >> 2, t4 = lane & 3;
    const int qbase = qt * BM, wrow = wid * 32;

    const size_t bh = (size_t)(b * Hv + h);
    const float* qp    = q + bh * Sv * Dv;
    const float* kp    = k + bh * Sv * Dv;
    const float* vp    = v + bh * Sv * Dv;
    const float* biasp = bias + (size_t)h * Sv * Sv;
    const uint32_t* pm = g_mask + (size_t)b * Sv * MASK_WORDS_PER_ROW;
    float* op = out + bh * Sv * Dv;
    float* ap = out + (size_t)Bv * Hv * Sv * Dv + bh * (size_t)Sv * Sv;

    // ---- group 0: Q + K0 + V0 ----
    for (int i = tid; i < BM * Dv / 4; i += THREADS) {
        int r = i >> 4, c = (i & 15) * 4;
        cpa16(sb + SQ + (r * LDSK + c) * 4, qp + (size_t)(qbase + r) * Dv + c);
    }
    for (int i = tid; i < BN * Dv / 4; i += THREADS) {
        int r = i >> 4, c = (i & 15) * 4;
        cpa16(sb + SK0 + (r * LDSK + c) * 4, kp + (size_t)r * Dv + c);
        cpa16(sb + SV0 + (r * LDSK + c) * 4, vp + (size_t)r * Dv + c);
    }
    asm volatile("cp.async.commit_group;" ::: "memory");

    // wait group 0, then rna-convert Q in place (once)
    asm volatile("cp.async.wait_group 0;" ::: "memory");
    __syncthreads();
    for (int i = tid; i < BM * Dv / 4; i += THREADS) {
        int r = i >> 4, c = (i & 15) * 4;
        uint32_t* p = sQ + r * LDSK + c;
        float4 f = *reinterpret_cast<const float4*>(p);
        p[0] = f2tf(f.x); p[1] = f2tf(f.y); p[2] = f2tf(f.z); p[3] = f2tf(f.w);
    }
    __syncthreads();

    const uint32_t* sQa0 = sQ + (wrow + g) * LDSK + t4;
    const uint32_t* sQa1 = sQ + (wrow + 16 + g) * LDSK + t4;
    const int rA0 = qbase + wrow + g;
    const int rA1 = qbase + wrow + 16 + g;

    const int srcA = (lane & 28) | (t4 >> 1);
    const int srcB = srcA + 2;
    const int sel  = t4 & 1;
    const int bsh  = 2 * t4;   // bit shift base within each 8-col group

    float ls[2][2] = {{0.f, 0.f}, {0.f, 0.f}};
    float o[2][8][4];
    #pragma unroll
    for (int mb = 0; mb < 2; mb++)
        #pragma unroll
        for (int dt = 0; dt < 8; dt++)
            o[mb][dt][0] = o[mb][dt][1] = o[mb][dt][2] = o[mb][dt][3] = 0.f;

    for (int kt = 0; kt < NKT; kt++) {
        const int cur = kt & 1;
        // prefetch next tile into the other buffer
        if (kt + 1 < NKT) {
            const uint32_t dk = sb + (cur ? SK0 : SK1);
            const uint32_t dv = sb + (cur ? SV0 : SV1);
            const float* ks = kp + (size_t)(kt + 1) * BN * Dv;
            const float* vs = vp + (size_t)(kt + 1) * BN * Dv;
            for (int i = tid; i < BN * Dv / 4; i += THREADS) {
                int r = i >> 4, c = (i & 15) * 4;
                cpa16(dk + (r * LDSK + c) * 4, ks + (size_t)r * Dv + c);
                cpa16(dv + (r * LDSK + c) * 4, vs + (size_t)r * Dv + c);
            }
            asm volatile("cp.async.commit_group;" ::: "memory");
            asm volatile("cp.async.wait_group 1;" ::: "memory");
        } else {
            asm volatile("cp.async.wait_group 0;" ::: "memory");
        }
        __syncthreads();

        const float* sK = (float*)(smem + (cur ? SK1 : SK0));
        const float* sV = (float*)(smem + (cur ? SV1 : SV0));

        // packed mask words for this tile's 64 columns, all 4 owned rows
        const uint2 mwA0 = *reinterpret_cast<const uint2*>(pm + (size_t)rA0 * MASK_WORDS_PER_ROW + kt * 2);
        const uint2 mwB0 = *reinterpret_cast<const uint2*>(pm + (size_t)(rA0 + 8) * MASK_WORDS_PER_ROW + kt * 2);
        const uint2 mwA1 = *reinterpret_cast<const uint2*>(pm + (size_t)rA1 * MASK_WORDS_PER_ROW + kt * 2);
        const uint2 mwB1 = *reinterpret_cast<const uint2*>(pm + (size_t)(rA1 + 8) * MASK_WORDS_PER_ROW + kt * 2);

        // ---- QK ----
        float acc[2][8][4];
        #pragma unroll
        for (int mb = 0; mb < 2; mb++)
            #pragma unroll
            for (int nt = 0; nt < 8; nt++)
                acc[mb][nt][0] = acc[mb][nt][1] = acc[mb][nt][2] = acc[mb][nt][3] = 0.f;

        #pragma unroll
        for (int kk = 0; kk < 8; kk++) {
            uint32_t a0[4], a1[4];
            a0[0] = sQa0[kk * 8];                a1[0] = sQa1[kk * 8];
            a0[1] = sQa0[kk * 8 + 8 * LDSK];     a1[1] = sQa1[kk * 8 + 8 * LDSK];
            a0[2] = sQa0[kk * 8 + 4];            a1[2] = sQa1[kk * 8 + 4];
            a0[3] = sQa0[kk * 8 + 8 * LDSK + 4]; a1[3] = sQa1[kk * 8 + 8 * LDSK + 4];
            #pragma unroll
            for (int nt = 0; nt < 8; nt++) {
                const float* kb = sK + (nt * 8 + g) * LDSK + kk * 8 + t4;
                uint32_t b0 = f2tf(kb[0]), b1 = f2tf(kb[4]);
                mma8(acc[0][nt], a0, b0, b1);
                mma8(acc[1][nt], a1, b0, b1);
            }
        }

        // ---- epilogue: e = exp(masked score + bias), unnormalized streaming attn write ----
        #pragma unroll
        for (int mb = 0; mb < 2; mb++) {
            const int rowA = (mb ? rA1 : rA0);
            const int rowB = rowA + 8;
            const uint2 mwA = (mb ? mwA1 : mwA0);
            const uint2 mwB = (mb ? mwB1 : mwB0);
            #pragma unroll
            for (int nt = 0; nt < 8; nt++) {
                const uint32_t wa = (nt < 4) ? mwA.x : mwA.y;
                const uint32_t wb = (nt < 4) ? mwB.x : mwB.y;
                const int sh = (nt & 3) * 8 + bsh;
                int col = kt * BN + nt * 8 + 2 * t4;
                float2 bA = *reinterpret_cast<const float2*>(biasp + (size_t)rowA * Sv + col);
                float2 bB = *reinterpret_cast<const float2*>(biasp + (size_t)rowB * Sv + col);
                float s0 = (((wa >> sh) & 1u)       ? acc[mb][nt][0] * 0.125f : NEG_INF) + bA.x;
                float s1 = (((wa >> (sh + 1)) & 1u) ? acc[mb][nt][1] * 0.125f : NEG_INF) + bA.y;
                float s2 = (((wb >> sh) & 1u)       ? acc[mb][nt][2] * 0.125f : NEG_INF) + bB.x;
                float s3 = (((wb >> (sh + 1)) & 1u) ? acc[mb][nt][3] * 0.125f : NEG_INF) + bB.y;
                float e0 = __expf(fminf(s0, 60.f));
                float e1 = __expf(fminf(s1, 60.f));
                float e2 = __expf(fminf(s2, 60.f));
                float e3 = __expf(fminf(s3, 60.f));
                st_cs2(ap + (size_t)rowA * Sv + col, e0, e1);
                st_cs2(ap + (size_t)rowB * Sv + col, e2, e3);
                ls[mb][0] += e0 + e1;
                ls[mb][1] += e2 + e3;
                acc[mb][nt][0] = e0; acc[mb][nt][1] = e1;
                acc[mb][nt][2] = e2; acc[mb][nt][3] = e3;
            }
        }

        // ---- PV: remap acc (C-frag) -> A-frag via shuffles, rna-round, accumulate O ----
        #pragma unroll
        for (int kk = 0; kk < 8; kk++) {
            uint32_t a0[4], a1[4];
            {
                float u0 = __shfl_sync(0xffffffffu, acc[0][kk][0], srcA);
                float u1 = __shfl_sync(0xffffffffu, acc[0][kk][1], srcA);
                float u2 = __shfl_sync(0xffffffffu, acc[0][kk][2], srcA);
                float u3 = __shfl_sync(0xffffffffu, acc[0][kk][3], srcA);
                float w0 = __shfl_sync(0xffffffffu, acc[0][kk][0], srcB);
                float w1 = __shfl_sync(0xffffffffu, acc[0][kk][1], srcB);
                float w2 = __shfl_sync(0xffffffffu, acc[0][kk][2], srcB);
                float w3 = __shfl_sync(0xffffffffu, acc[0][kk][3], srcB);
                a0[0] = f2tf(sel ? u1 : u0);  a0[1] = f2tf(sel ? u3 : u2);
                a0[2] = f2tf(sel ? w1 : w0);  a0[3] = f2tf(sel ? w3 : w2);
            }
            {
                float u0 = __shfl_sync(0xffffffffu, acc[1][kk][0], srcA);
                float u1 = __shfl_sync(0xffffffffu, acc[1][kk][1], srcA);
                float u2 = __shfl_sync(0xffffffffu, acc[1][kk][2], srcA);
                float u3 = __shfl_sync(0xffffffffu, acc[1][kk][3], srcA);
                float w0 = __shfl_sync(0xffffffffu, acc[1][kk][0], srcB);
                float w1 = __shfl_sync(0xffffffffu, acc[1][kk][1], srcB);
                float w2 = __shfl_sync(0xffffffffu, acc[1][kk][2], srcB);
                float w3 = __shfl_sync(0xffffffffu, acc[1][kk][3], srcB);
                a1[0] = f2tf(sel ? u1 : u0);  a1[1] = f2tf(sel ? u3 : u2);
                a1[2] = f2tf(sel ? w1 : w0);  a1[3] = f2tf(sel ? w3 : w2);
            }
            #pragma unroll
            for (int dt = 0; dt < 8; dt++) {
                const float* vb = sV + (kk * 8 + t4) * LDSK + dt * 8 + g;
                uint32_t b0 = f2tf(vb[0]), b1 = f2tf(vb[4 * LDSK]);
                mma8(o[0][dt], a0, b0, b1);
                mma8(o[1][dt], a1, b0, b1);
            }
        }
        __syncthreads();  // done reading bufs before next iter's prefetch overwrites
    }

    // ---- row sums -> inverses (reduce across t4 quad) ----
    #pragma unroll
    for (int mb = 0; mb < 2; mb++) {
        ls[mb][0] += __shfl_xor_sync(0xffffffffu, ls[mb][0], 1);
        ls[mb][0] += __shfl_xor_sync(0xffffffffu, ls[mb][0], 2);
        ls[mb][1] += __shfl_xor_sync(0xffffffffu, ls[mb][1], 1);
        ls[mb][1] += __shfl_xor_sync(0xffffffffu, ls[mb][1], 2);
    }
    const float il[2][2] = {{1.f / ls[0][0], 1.f / ls[0][1]},
                            {1.f / ls[1][0], 1.f / ls[1][1]}};

    // stash inverses for the normalize kernel
    if (t4 == 0) {
        #pragma unroll
        for (int mb = 0; mb < 2; mb++) {
            const int rowA = (mb ? rA1 : rA0);
            g_inv[bh * Sv + rowA]     = il[mb][0];
            g_inv[bh * Sv + rowA + 8] = il[mb][1];
        }
    }

    // ---- write O (normalized) ----
    #pragma unroll
    for (int mb = 0; mb < 2; mb++) {
        const int rowA = (mb ? rA1 : rA0);
        const int rowB = rowA + 8;
        #pragma unroll
        for (int dt = 0; dt < 8; dt++) {
            int col = dt * 8 + 2 * t4;
            *reinterpret_cast<float2*>(op + (size_t)rowA * Dv + col) =
                make_float2(o[mb][dt][0] * il[mb][0], o[mb][dt][1] * il[mb][0]);
            *reinterpret_cast<float2*>(op + (size_t)rowB * Dv + col) =
                make_float2(o[mb][dt][2] * il[mb][1], o[mb][dt][3] * il[mb][1]);
        }
    }
}

// ---- pass 2: attn[row] *= 1/lsum[row] (pure stream, single-touch hints) ----
__global__ __launch_bounds__(256)
void sdpa_normalize_kernel(float4* __restrict__ attn, int64_t total4)
{
    int64_t stride = (int64_t)gridDim.x * blockDim.x;
    for (int64_t i = (int64_t)blockIdx.x * blockDim.x + threadIdx.x; i < total4; i += stride) {
        float inv = g_inv[i >> 9];   // 512 float4 per 2048-col row
        float4 vv = __ldcs(attn + i);
        vv.x *= inv; vv.y *= inv; vv.z *= inv; vv.w *= inv;
        __stcs(attn + i, vv);
    }
}

extern "C" void kernel_launch(void* const* d_in, const int* in_sizes, int n_in,
                              void* d_out, int out_size)
{
    const float* q    = (const float*)d_in[0];
    const float* k    = (const float*)d_in[1];
    const float* v    = (const float*)d_in[2];
    const int*   mask = (const int*)d_in[3];
    const float* bias = (const float*)d_in[4];
    float* out = (float*)d_out;

    // pass 0: pack mask bits (one warp per 32-col word)
    sdpa_pack_mask_kernel<<<Bv * Sv * MASK_WORDS_PER_ROW / 8, 256>>>(mask);

    cudaFuncSetAttribute(ScaledDotProductAttention_30253749633177_kernel,
                         cudaFuncAttributeMaxDynamicSharedMemorySize, SMEM_TOTAL);

    dim3 grid(Bv * Hv, Sv / BM);   // x = all (b,h) for one qt -> mask+bias L2 co-residency
    ScaledDotProductAttention_30253749633177_kernel<<<grid, THREADS, SMEM_TOTAL>>>(
        q, k, v, bias, out);

    float4* attn = (float4*)(out + (size_t)Bv * Hv * Sv * Dv);
    int64_t total4 = (int64_t)Bv * Hv * Sv * Sv / 4;
    sdpa_normalize_kernel<<<8192, 256>>>(attn, total4);
}

// round 9
// speedup vs baseline: 1.2542x; 1.0332x over previous
#include <cuda_runtime.h>
#include <cstdint>

// ScaledDotProductAttention  B=4 H=16 S=2048 D=64
// out = [output (B,H,S,D) | attn (B,H,S,S)] f32.
// R9 = R8 + pre-converted/permuted K' V' gmem images (tf32 + pair layouts) so the
// hot loop's B-fragments are single conflict-free LDS.64 with no cvt; faster mask pack.

#define NEG_INF -1000000000.0f

static constexpr int Bv = 4, Hv = 16, Sv = 2048, Dv = 64;
static constexpr int BM = 128, BN = 64, THREADS = 128, NKT = Sv / BN;
static constexpr int LDSK = 72;    // Q/K smem row stride (words): 64-bit pair-bank = 4g+t4, conflict-free
static constexpr int LDSV = 136;   // V' smem pair-row stride (words): pair-bank = 4*t4+g, conflict-free

// smem byte offsets: Q | K0 | K1 | V0 | V1
static constexpr int SQ  = 0;
static constexpr int QB  = BM * LDSK * 4;             // 36864
static constexpr int KTB = BN * LDSK * 4;             // 18432
static constexpr int VTB = 32 * LDSV * 4;             // 17408
static constexpr int SK0 = QB;
static constexpr int SK1 = SK0 + KTB;
static constexpr int SV0 = SK1 + KTB;
static constexpr int SV1 = SV0 + VTB;
static constexpr int SMEM_TOTAL = SV1 + VTB;          // 108544

static constexpr int MASK_WORDS_PER_ROW = Sv / 32;    // 64

__device__ float    g_inv[Bv * Hv * Sv];
__device__ uint32_t g_mask[Bv * Sv * MASK_WORDS_PER_ROW];           // 2 MB
__device__ uint32_t g_kperm[Bv * Hv * Sv * Dv];                     // 33.5 MB K' (tf32, col pair-perm)
__device__ uint32_t g_vperm[Bv * Hv * Sv * Dv];                     // 33.5 MB V' (tf32, row-pair transp)

__device__ __forceinline__ uint32_t s2u(const void* p) {
    uint32_t a;
    asm("{ .reg .u64 t; cvta.to.shared.u64 t, %1; cvt.u32.u64 %0, t; }" : "=r"(a) : "l"(p));
    return a;
}
__device__ __forceinline__ void cpa16(uint32_t dst, const void* src) {
    asm volatile("cp.async.cg.shared.global [%0], [%1], 16;" :: "r"(dst), "l"(src));
}
__device__ __forceinline__ uint32_t f2tf(float f) {
    uint32_t u;
    asm("cvt.rna.tf32.f32 %0, %1;" : "=r"(u) : "f"(f));
    return u;
}
__device__ __forceinline__ void st_cs2(float* p, float x, float y) {
    asm volatile("st.global.cs.v2.f32 [%0], {%1, %2};" :: "l"(p), "f"(x), "f"(y) : "memory");
}
__device__ __forceinline__ void mma8(float c[4], const uint32_t a[4], uint32_t b0, uint32_t b1) {
    asm volatile(
        "mma.sync.aligned.m16n8k8.row.col.f32.tf32.tf32.f32 "
        "{%0,%1,%2,%3}, {%4,%5,%6,%7}, {%8,%9}, {%0,%1,%2,%3};"
        : "+f"(c[0]), "+f"(c[1]), "+f"(c[2]), "+f"(c[3])
        : "r"(a[0]), "r"(a[1]), "r"(a[2]), "r"(a[3]), "r"(b0), "r"(b1));
}

// ---- pass 0a: pack mask to bits (int4 + shfl-compose; 8 threads per word) ----
__global__ __launch_bounds__(256)
void sdpa_pack_mask_kernel(const int* __restrict__ mask)
{
    int gid = blockIdx.x * blockDim.x + threadIdx.x;      // over Bv*Sv*Sv/4
    int4 m = *reinterpret_cast<const int4*>(mask + (size_t)gid * 4);
    uint32_t nib = (m.x != 0) | ((m.y != 0) << 1) | ((m.z != 0) << 2) | ((m.w != 0) << 3);
    uint32_t v = nib << (4 * (gid & 7));
    v |= __shfl_xor_sync(0xffffffffu, v, 1);
    v |= __shfl_xor_sync(0xffffffffu, v, 2);
    v |= __shfl_xor_sync(0xffffffffu, v, 4);
    if ((gid & 7) == 0) g_mask[gid >> 3] = v;
}

// ---- pass 0b: K' = tf32(K) with cols pair-permuted within each 8-block ----
__global__ __launch_bounds__(256)
void sdpa_prep_k_kernel(const float* __restrict__ k)
{
    int gid = blockIdx.x * blockDim.x + threadIdx.x;      // over rows*8
    int row = gid >> 3, b8 = gid & 7;
    const float* src = k + (size_t)row * Dv + b8 * 8;
    float4 lo = *reinterpret_cast<const float4*>(src);
    float4 hi = *reinterpret_cast<const float4*>(src + 4);
    uint32_t* dst = g_kperm + (size_t)row * Dv + b8 * 8;
    uint4 d0 = make_uint4(f2tf(lo.x), f2tf(hi.x), f2tf(lo.y), f2tf(hi.y));
    uint4 d1 = make_uint4(f2tf(lo.z), f2tf(hi.z), f2tf(lo.w), f2tf(hi.w));
    *reinterpret_cast<uint4*>(dst)     = d0;
    *reinterpret_cast<uint4*>(dst + 4) = d1;
}

// ---- pass 0c: V' = tf32(V), row-pair transposed: tile[p][c][2] with p=kk*4+t4,
//               rows (kk*8+t4, kk*8+t4+4); tile = 4096 words contiguous ----
__global__ __launch_bounds__(256)
void sdpa_prep_v_kernel(const float* __restrict__ v)
{
    int gid = blockIdx.x * blockDim.x + threadIdx.x;      // over total/4 float4s
    int tile = gid >> 10;                                 // bh*NKT + kt
    int q    = gid & 1023;
    int p = q >> 5, u = q & 31;
    int c = u * 2;
    int r0 = (p >> 2) * 8 + (p & 3);
    const float* base = v + (size_t)tile * BN * Dv;
    float2 a = *reinterpret_cast<const float2*>(base + (size_t)r0 * Dv + c);
    float2 b = *reinterpret_cast<const float2*>(base + (size_t)(r0 + 4) * Dv + c);
    uint4 d = make_uint4(f2tf(a.x), f2tf(b.x), f2tf(a.y), f2tf(b.y));
    *reinterpret_cast<uint4*>(g_vperm + (size_t)gid * 4) = d;
}

__global__ __launch_bounds__(THREADS, 2)
void ScaledDotProductAttention_30253749633177_kernel(
    const float* __restrict__ q, const float* __restrict__ bias,
    float* __restrict__ out)
{
    extern __shared__ char smem[];
    const uint32_t sb = s2u(smem);
    uint32_t* sQ = (uint32_t*)(smem + SQ);

    const int b  = blockIdx.x & 3;      // (b,h) collapsed for mask+bias L2 co-residency
    const int h  = blockIdx.x >> 2;
    const int qt = blockIdx.y;
    const int tid = threadIdx.x;
    const int wid = tid >> 5, lane = tid & 31;
    const int g = lane >> 2, t4 = lane & 3;
    const int qbase = qt * BM, wrow = wid * 32;

    const size_t bh = (size_t)(b * Hv + h);
    const float*    qp = q + bh * Sv * Dv;
    const uint32_t* kp = g_kperm + bh * Sv * Dv;
    const uint32_t* vp = g_vperm + bh * Sv * Dv;   // tile kt at +kt*4096
    const float* biasp = bias + (size_t)h * Sv * Sv;
    const uint32_t* pm = g_mask + (size_t)b * Sv * MASK_WORDS_PER_ROW;
    float* op = out + bh * Sv * Dv;
    float* ap = out + (size_t)Bv * Hv * Sv * Dv + bh * (size_t)Sv * Sv;

    // ---- group 0: Q + K0 + V0 ----
    for (int i = tid; i < BM * Dv / 4; i += THREADS) {
        int r = i >> 4, c = (i & 15) * 4;
        cpa16(sb + SQ + (r * LDSK + c) * 4, qp + (size_t)(qbase + r) * Dv + c);
    }
    for (int i = tid; i < BN * Dv / 4; i += THREADS) {
        int r = i >> 4, c = (i & 15) * 4;
        cpa16(sb + SK0 + (r * LDSK + c) * 4, kp + (size_t)r * Dv + c);
    }
    for (int i = tid; i < 1024; i += THREADS) {
        int p = i >> 5, u = i & 31;
        cpa16(sb + SV0 + (p * LDSV + u * 4) * 4, vp + (size_t)i * 4);
    }
    asm volatile("cp.async.commit_group;" ::: "memory");

    // wait group 0, then rna-convert + pair-permute Q in place (once; one row/thread)
    asm volatile("cp.async.wait_group 0;" ::: "memory");
    __syncthreads();
    {
        uint32_t* qr = sQ + tid * LDSK;
        float f[64];
        #pragma unroll
        for (int i = 0; i < 16; i++) {
            float4 x = *reinterpret_cast<const float4*>(qr + i * 4);
            f[i*4+0] = x.x; f[i*4+1] = x.y; f[i*4+2] = x.z; f[i*4+3] = x.w;
        }
        #pragma unroll
        for (int b8 = 0; b8 < 8; b8++)
            #pragma unroll
            for (int i = 0; i < 4; i++) {
                qr[b8*8 + 2*i]     = f2tf(f[b8*8 + i]);
                qr[b8*8 + 2*i + 1] = f2tf(f[b8*8 + i + 4]);
            }
    }
    __syncthreads();

    const uint32_t* sQr0 = sQ + (wrow + g) * LDSK;
    const uint32_t* sQr1 = sQ + (wrow + 16 + g) * LDSK;
    const int rA0 = qbase + wrow + g;
    const int rA1 = qbase + wrow + 16 + g;

    const int srcA = (lane & 28) | (t4 >> 1);
    const int srcB = srcA + 2;
    const int sel  = t4 & 1;
    const int bsh  = 2 * t4;

    float ls[2][2] = {{0.f, 0.f}, {0.f, 0.f}};
    float o[2][8][4];
    #pragma unroll
    for (int mb = 0; mb < 2; mb++)
        #pragma unroll
        for (int dt = 0; dt < 8; dt++)
            o[mb][dt][0] = o[mb][dt][1] = o[mb][dt][2] = o[mb][dt][3] = 0.f;

    for (int kt = 0; kt < NKT; kt++) {
        const int cur = kt & 1;
        if (kt + 1 < NKT) {
            const uint32_t dk = sb + (cur ? SK0 : SK1);
            const uint32_t dv = sb + (cur ? SV0 : SV1);
            const uint32_t* ks = kp + (size_t)(kt + 1) * BN * Dv;
            const uint32_t* vs = vp + (size_t)(kt + 1) * 4096;
            for (int i = tid; i < BN * Dv / 4; i += THREADS) {
                int r = i >> 4, c = (i & 15) * 4;
                cpa16(dk + (r * LDSK + c) * 4, ks + (size_t)r * Dv + c);
            }
            for (int i = tid; i < 1024; i += THREADS) {
                int p = i >> 5, u = i & 31;
                cpa16(dv + (p * LDSV + u * 4) * 4, vs + (size_t)i * 4);
            }
            asm volatile("cp.async.commit_group;" ::: "memory");
            asm volatile("cp.async.wait_group 1;" ::: "memory");
        } else {
            asm volatile("cp.async.wait_group 0;" ::: "memory");
        }
        __syncthreads();

        const uint32_t* sK  = (const uint32_t*)(smem + (cur ? SK1 : SK0));
        const uint32_t* sVp = (const uint32_t*)(smem + (cur ? SV1 : SV0));

        const uint2 mwA0 = *reinterpret_cast<const uint2*>(pm + (size_t)rA0 * MASK_WORDS_PER_ROW + kt * 2);
        const uint2 mwB0 = *reinterpret_cast<const uint2*>(pm + (size_t)(rA0 + 8) * MASK_WORDS_PER_ROW + kt * 2);
        const uint2 mwA1 = *reinterpret_cast<const uint2*>(pm + (size_t)rA1 * MASK_WORDS_PER_ROW + kt * 2);
        const uint2 mwB1 = *reinterpret_cast<const uint2*>(pm + (size_t)(rA1 + 8) * MASK_WORDS_PER_ROW + kt * 2);

        // ---- QK (all LDS.64, no cvt) ----
        float acc[2][8][4];
        #pragma unroll
        for (int mb = 0; mb < 2; mb++)
            #pragma unroll
            for (int nt = 0; nt < 8; nt++)
                acc[mb][nt][0] = acc[mb][nt][1] = acc[mb][nt][2] = acc[mb][nt][3] = 0.f;

        #pragma unroll
        for (int kk = 0; kk < 8; kk++) {
            const int co = kk * 8 + 2 * t4;
            uint32_t a0[4], a1[4];
            uint2 p0 = *reinterpret_cast<const uint2*>(sQr0 + co);
            uint2 p1 = *reinterpret_cast<const uint2*>(sQr0 + 8 * LDSK + co);
            uint2 p2 = *reinterpret_cast<const uint2*>(sQr1 + co);
            uint2 p3 = *reinterpret_cast<const uint2*>(sQr1 + 8 * LDSK + co);
            a0[0] = p0.x; a0[1] = p1.x; a0[2] = p0.y; a0[3] = p1.y;
            a1[0] = p2.x; a1[1] = p3.x; a1[2] = p2.y; a1[3] = p3.y;
            #pragma unroll
            for (int nt = 0; nt < 8; nt++) {
                uint2 bb = *reinterpret_cast<const uint2*>(sK + (nt * 8 + g) * LDSK + co);
                mma8(acc[0][nt], a0, bb.x, bb.y);
                mma8(acc[1][nt], a1, bb.x, bb.y);
            }
        }

        // ---- epilogue ----
        #pragma unroll
        for (int mb = 0; mb < 2; mb++) {
            const int rowA = (mb ? rA1 : rA0);
            const int rowB = rowA + 8;
            const uint2 mwA = (mb ? mwA1 : mwA0);
            const uint2 mwB = (mb ? mwB1 : mwB0);
            #pragma unroll
            for (int nt = 0; nt < 8; nt++) {
                const uint32_t wa = (nt < 4) ? mwA.x : mwA.y;
                const uint32_t wb = (nt < 4) ? mwB.x : mwB.y;
                const int sh = (nt & 3) * 8 + bsh;
                int col = kt * BN + nt * 8 + 2 * t4;
                float2 bA = *reinterpret_cast<const float2*>(biasp + (size_t)rowA * Sv + col);
                float2 bB = *reinterpret_cast<const float2*>(biasp + (size_t)rowB * Sv + col);
                float s0 = (((wa >> sh) & 1u)       ? acc[mb][nt][0] * 0.125f : NEG_INF) + bA.x;
                float s1 = (((wa >> (sh + 1)) & 1u) ? acc[mb][nt][1] * 0.125f : NEG_INF) + bA.y;
                float s2 = (((wb >> sh) & 1u)       ? acc[mb][nt][2] * 0.125f : NEG_INF) + bB.x;
                float s3 = (((wb >> (sh + 1)) & 1u) ? acc[mb][nt][3] * 0.125f : NEG_INF) + bB.y;
                float e0 = __expf(fminf(s0, 60.f));
                float e1 = __expf(fminf(s1, 60.f));
                float e2 = __expf(fminf(s2, 60.f));
                float e3 = __expf(fminf(s3, 60.f));
                st_cs2(ap + (size_t)rowA * Sv + col, e0, e1);
                st_cs2(ap + (size_t)rowB * Sv + col, e2, e3);
                ls[mb][0] += e0 + e1;
                ls[mb][1] += e2 + e3;
                acc[mb][nt][0] = e0; acc[mb][nt][1] = e1;
                acc[mb][nt][2] = e2; acc[mb][nt][3] = e3;
            }
        }

        // ---- PV: shfl remap -> rna -> MMA; V' pairs are LDS.64, no cvt ----
        #pragma unroll
        for (int kk = 0; kk < 8; kk++) {
            uint32_t a0[4], a1[4];
            {
                float u0 = __shfl_sync(0xffffffffu, acc[0][kk][0], srcA);
                float u1 = __shfl_sync(0xffffffffu, acc[0][kk][1], srcA);
                float u2 = __shfl_sync(0xffffffffu, acc[0][kk][2], srcA);
                float u3 = __shfl_sync(0xffffffffu, acc[0][kk][3], srcA);
                float w0 = __shfl_sync(0xffffffffu, acc[0][kk][0], srcB);
                float w1 = __shfl_sync(0xffffffffu, acc[0][kk][1], srcB);
                float w2 = __shfl_sync(0xffffffffu, acc[0][kk][2], srcB);
                float w3 = __shfl_sync(0xffffffffu, acc[0][kk][3], srcB);
                a0[0] = f2tf(sel ? u1 : u0);  a0[1] = f2tf(sel ? u3 : u2);
                a0[2] = f2tf(sel ? w1 : w0);  a0[3] = f2tf(sel ? w3 : w2);
            }
            {
                float u0 = __shfl_sync(0xffffffffu, acc[1][kk][0], srcA);
                float u1 = __shfl_sync(0xffffffffu, acc[1][kk][1], srcA);
                float u2 = __shfl_sync(0xffffffffu, acc[1][kk][2], srcA);
                float u3 = __shfl_sync(0xffffffffu, acc[1][kk][3], srcA);
                float w0 = __shfl_sync(0xffffffffu, acc[1][kk][0], srcB);
                float w1 = __shfl_sync(0xffffffffu, acc[1][kk][1], srcB);
                float w2 = __shfl_sync(0xffffffffu, acc[1][kk][2], srcB);
                float w3 = __shfl_sync(0xffffffffu, acc[1][kk][3], srcB);
                a1[0] = f2tf(sel ? u1 : u0);  a1[1] = f2tf(sel ? u3 : u2);
                a1[2] = f2tf(sel ? w1 : w0);  a1[3] = f2tf(sel ? w3 : w2);
            }
            #pragma unroll
            for (int dt = 0; dt < 8; dt++) {
                uint2 vv = *reinterpret_cast<const uint2*>(sVp + (kk * 4 + t4) * LDSV + (dt * 8 + g) * 2);
                mma8(o[0][dt], a0, vv.x, vv.y);
                mma8(o[1][dt], a1, vv.x, vv.y);
            }
        }
        __syncthreads();
    }

    // ---- row sums -> inverses ----
    #pragma unroll
    for (int mb = 0; mb < 2; mb++) {
        ls[mb][0] += __shfl_xor_sync(0xffffffffu, ls[mb][0], 1);
        ls[mb][0] += __shfl_xor_sync(0xffffffffu, ls[mb][0], 2);
        ls[mb][1] += __shfl_xor_sync(0xffffffffu, ls[mb][1], 1);
        ls[mb][1] += __shfl_xor_sync(0xffffffffu, ls[mb][1], 2);
    }
    const float il[2][2] = {{1.f / ls[0][0], 1.f / ls[0][1]},
                            {1.f / ls[1][0], 1.f / ls[1][1]}};

    if (t4 == 0) {
        #pragma unroll
        for (int mb = 0; mb < 2; mb++) {
            const int rowA = (mb ? rA1 : rA0);
            g_inv[bh * Sv + rowA]     = il[mb][0];
            g_inv[bh * Sv + rowA + 8] = il[mb][1];
        }
    }

    #pragma unroll
    for (int mb = 0; mb < 2; mb++) {
        const int rowA = (mb ? rA1 : rA0);
        const int rowB = rowA + 8;
        #pragma unroll
        for (int dt = 0; dt < 8; dt++) {
            int col = dt * 8 + 2 * t4;
            *reinterpret_cast<float2*>(op + (size_t)rowA * Dv + col) =
                make_float2(o[mb][dt][0] * il[mb][0], o[mb][dt][1] * il[mb][0]);
            *reinterpret_cast<float2*>(op + (size_t)rowB * Dv + col) =
                make_float2(o[mb][dt][2] * il[mb][1], o[mb][dt][3] * il[mb][1]);
        }
    }
}

// ---- pass 2: attn[row] *= 1/lsum[row] ----
__global__ __launch_bounds__(256)
void sdpa_normalize_kernel(float4* __restrict__ attn, int64_t total4)
{
    int64_t stride = (int64_t)gridDim.x * blockDim.x;
    for (int64_t i = (int64_t)blockIdx.x * blockDim.x + threadIdx.x; i < total4; i += stride) {
        float inv = g_inv[i >> 9];
        float4 vv = __ldcs(attn + i);
        vv.x *= inv; vv.y *= inv; vv.z *= inv; vv.w *= inv;
        __stcs(attn + i, vv);
    }
}

extern "C" void kernel_launch(void* const* d_in, const int* in_sizes, int n_in,
                              void* d_out, int out_size)
{
    const float* q    = (const float*)d_in[0];
    const float* k    = (const float*)d_in[1];
    const float* v    = (const float*)d_in[2];
    const int*   mask = (const int*)d_in[3];
    const float* bias = (const float*)d_in[4];
    float* out = (float*)d_out;

    sdpa_pack_mask_kernel<<<Bv * Sv * Sv / 4 / 256, 256>>>(mask);
    sdpa_prep_k_kernel<<<Bv * Hv * Sv * 8 / 256, 256>>>(k);
    sdpa_prep_v_kernel<<<Bv * Hv * Sv * Dv / 4 / 256, 256>>>(v);

    cudaFuncSetAttribute(ScaledDotProductAttention_30253749633177_kernel,
                         cudaFuncAttributeMaxDynamicSharedMemorySize, SMEM_TOTAL);

    dim3 grid(Bv * Hv, Sv / BM);
    ScaledDotProductAttention_30253749633177_kernel<<<grid, THREADS, SMEM_TOTAL>>>(
        q, bias, out);

    float4* attn = (float4*)(out + (size_t)Bv * Hv * Sv * Dv);
    int64_t total4 = (int64_t)Bv * Hv * Sv * Sv / 4;
    sdpa_normalize_kernel<<<8192, 256>>>(attn, total4);
}